// round 17
// baseline (speedup 1.0000x reference)
#include <cuda_runtime.h>
#include <cuda_fp16.h>
#include <cstdint>

#define BB 256
#define TT 2048

// ---------- scratch ----------
__device__ __half g_out1h[(size_t)BB * TT * 128];   // layer-1 output fp16 [B,T,128] (fwd|bwd)
__device__ float  g_pre2p[(size_t)BB * TT * 256];   // l2 input preact, permuted [s][t][j*4+gate], bias folded, i/f/o pre-halved
__device__ __half g_B2i[256 * 128];                 // pre2 GEMM B: Wih2 fp16, col n2=j*4+gate, i/f/o halved

// ---------- helpers ----------
__device__ __forceinline__ float tanh_f(float x) {
    float y; asm("tanh.approx.f32 %0, %1;" : "=f"(y) : "f"(x)); return y;
}
__device__ __forceinline__ float sig_h(float x) {       // x pre-halved
    return fmaf(tanh_f(x), 0.5f, 0.5f);
}
__device__ __forceinline__ __half hi_h(float v) { return __float2half_rn(v); }
__device__ __forceinline__ __half lo_h(float v) {
    return __float2half_rn(v - __half2float(__float2half_rn(v)));
}
__device__ __forceinline__ uint32_t pack2(float a, float b) {
    __half2 h = __floats2half2_rn(a, b);
    return *(uint32_t*)&h;
}
__device__ __forceinline__ uint32_t smem_u32(const void* p) {
    uint32_t a;
    asm("{ .reg .u64 t; cvta.to.shared.u64 t, %1; cvt.u32.u64 %0, t; }" : "=r"(a) : "l"(p));
    return a;
}
__device__ __forceinline__ void ldsm4(uint32_t* r, uint32_t addr) {
    asm volatile("ldmatrix.sync.aligned.m8n8.x4.shared.b16 {%0,%1,%2,%3}, [%4];"
                 : "=r"(r[0]), "=r"(r[1]), "=r"(r[2]), "=r"(r[3]) : "r"(addr));
}
__device__ __forceinline__ void ldsm4t(uint32_t* r, uint32_t addr) {
    asm volatile("ldmatrix.sync.aligned.m8n8.x4.trans.shared.b16 {%0,%1,%2,%3}, [%4];"
                 : "=r"(r[0]), "=r"(r[1]), "=r"(r[2]), "=r"(r[3]) : "r"(addr));
}
__device__ __forceinline__ void ldsm2t(uint32_t* r, uint32_t addr) {
    asm volatile("ldmatrix.sync.aligned.m8n8.x2.trans.shared.b16 {%0,%1}, [%2];"
                 : "=r"(r[0]), "=r"(r[1]) : "r"(addr));
}
__device__ __forceinline__ void mma16816(float* d, const uint32_t* a, const uint32_t* b) {
    asm volatile("mma.sync.aligned.m16n8k16.row.col.f32.f16.f16.f32 "
                 "{%0,%1,%2,%3},{%4,%5,%6,%7},{%8,%9},{%0,%1,%2,%3};"
                 : "+f"(d[0]), "+f"(d[1]), "+f"(d[2]), "+f"(d[3])
                 : "r"(a[0]), "r"(a[1]), "r"(a[2]), "r"(a[3]), "r"(b[0]), "r"(b[1]));
}

// =====================================================================
// pre2 GEMM B build: col n2 = j*4+gate
// =====================================================================
__global__ void build_B2(const float* __restrict__ Wih2)
{
    const int n = blockIdx.x, k = threadIdx.x;
    const int g2 = n & 3;
    const int r2 = g2 * 64 + (n >> 2);
    const float s2 = (g2 == 2) ? 1.f : 0.5f;
    g_B2i[n * 128 + k] = __float2half_rn(s2 * Wih2[r2 * 128 + k]);
}

// =====================================================================
// Layer-1 scan (flipped + pipelined): 2 phase-offset groups of 4 samples.
// 8 samples/block, 64 blocks, 256 threads. Gates on M, samples dup'd on N.
// =====================================================================
#define HR1 80
__global__ __launch_bounds__(256, 1)
void l1_scan(const float* __restrict__ x,
             const float* __restrict__ Wih_f, const float* __restrict__ Whh_f, const float* __restrict__ b_f,
             const float* __restrict__ Wih_b, const float* __restrict__ Whh_b, const float* __restrict__ b_b)
{
    const int grp = blockIdx.x >> 1, dir = blockIdx.x & 1;
    const int s0  = grp * 8;
    const int tid = threadIdx.x, lane = tid & 31, w = tid >> 5;

    const float* Wih = dir ? Wih_b : Wih_f;
    const float* Whh = dir ? Whh_b : Whh_f;
    const float* bv  = dir ? b_b   : b_f;

    __shared__ __half HsA[HR1 * 8];
    __shared__ __half HsB[HR1 * 8];

    for (int i = tid; i < HR1 * 8; i += 256) { HsA[i] = __ushort_as_half(0); HsB[i] = __ushort_as_half(0); }

    const int jr = lane >> 2;
    const int j  = w * 8 + jr;
    const int sl = lane & 3;
    const int k0 = 2 * (lane & 3);

    // A fragments (weights, shared by both groups)
    uint32_t af[2][5][4];
#pragma unroll
    for (int tt = 0; tt < 2; tt++) {
        const int rA = (tt == 0 ? 0 : 2) * 64 + j;
        const int rB = (tt == 0 ? 1 : 3) * 64 + j;
        const float sA = (tt == 1) ? 1.f : 0.5f;
        const float sB = 0.5f;
#pragma unroll
        for (int kt = 0; kt < 5; kt++) {
            float a00, a01, a10, a11, a20, a21, a30, a31;
            if (kt < 4) {
                const float* pA = Whh + rA * 64 + kt * 16;
                const float* pB = Whh + rB * 64 + kt * 16;
                a00 = pA[k0];     a01 = pA[k0 + 1];
                a10 = pB[k0];     a11 = pB[k0 + 1];
                a20 = pA[k0 + 8]; a21 = pA[k0 + 9];
                a30 = pB[k0 + 8]; a31 = pB[k0 + 9];
            } else {
                a00 = (k0     < 4) ? Wih[rA * 4 + k0]     : Wih[rA * 4 + k0 - 4];
                a01 = (k0 + 1 < 4) ? Wih[rA * 4 + k0 + 1] : Wih[rA * 4 + k0 - 3];
                a10 = (k0     < 4) ? Wih[rB * 4 + k0]     : Wih[rB * 4 + k0 - 4];
                a11 = (k0 + 1 < 4) ? Wih[rB * 4 + k0 + 1] : Wih[rB * 4 + k0 - 3];
                a20 = 0.f; a21 = 0.f; a30 = 0.f; a31 = 0.f;
            }
            af[tt][kt][0] = pack2(sA * a00, sA * a01);
            af[tt][kt][1] = pack2(sB * a10, sB * a11);
            af[tt][kt][2] = pack2(sA * a20, sA * a21);
            af[tt][kt][3] = pack2(sB * a30, sB * a31);
        }
    }

    const float bi  = 0.5f * bv[j];
    const float bfv = 0.5f * bv[64 + j];
    const float bg  = bv[128 + j];
    const float bo  = 0.5f * bv[192 + j];

    const uint32_t baseA = smem_u32(HsA), baseB = smem_u32(HsB);
    const uint32_t adrA1 = baseA + lane * 16;
    const uint32_t adrA2 = baseA + (32 + lane) * 16;
    const uint32_t adrA3 = baseA + (64 + (lane & 15)) * 16;
    const uint32_t adrB1 = baseB + lane * 16;
    const uint32_t adrB2 = baseB + (32 + lane) * 16;
    const uint32_t adrB3 = baseB + (64 + (lane & 15)) * 16;

    const int step = dir ? -1 : 1;
    const int t0g  = dir ? TT - 1 : 0;

    // x feeders: threads 0..31; xg=0 -> group A, xg=1 -> group B
    const bool xfd = tid < 32;
    const int xg = (tid >> 4) & 1, fs = (tid >> 2) & 3, comp = tid & 3;
    const float* xp = x + ((size_t)(s0 + xg * 4 + fs) * TT + t0g) * 4 + comp;
    __half* HsX = xg ? HsB : HsA;
    float vn = 0.f, vi = 0.f;
    if (xfd) {
        float v0 = __ldg(xp);
        __half h0 = hi_h(v0), l0 = lo_h(v0);
        *(__half2*)&HsX[(64 + comp) * 8 + 2 * fs] = __halves2half2(h0, h0);
        *(__half2*)&HsX[(68 + comp) * 8 + 2 * fs] = __halves2half2(l0, l0);
        vn = __ldg(xp + step * 4);
        vi = __ldg(xp + 2 * step * 4);
    }
    __syncthreads();

    __half* outA = g_out1h + ((size_t)(s0 + sl) * TT + t0g) * 128 + dir * 64 + j;
    __half* outB = g_out1h + ((size_t)(s0 + 4 + sl) * TT + t0g) * 128 + dir * 64 + j;

    float cA = 0.f, cB = 0.f;

    // ---- prologue: B's step-0 matvec ----
    float Bt0A[4], Bt0B[4], Bt1A[4], Bt1B[4];
#pragma unroll
    for (int q = 0; q < 4; q++) { Bt0A[q] = 0.f; Bt0B[q] = 0.f; Bt1A[q] = 0.f; Bt1B[q] = 0.f; }
    {
        uint32_t bA[4], bB[4], bC[2];
        ldsm4t(bA, adrB1); ldsm4t(bB, adrB2); ldsm2t(bC, adrB3);
        mma16816(Bt0A, af[0][0], bA);      mma16816(Bt1A, af[1][0], bA);
        mma16816(Bt0A, af[0][1], bA + 2);  mma16816(Bt1A, af[1][1], bA + 2);
        mma16816(Bt0B, af[0][2], bB);      mma16816(Bt1B, af[1][2], bB);
        mma16816(Bt0B, af[0][3], bB + 2);  mma16816(Bt1B, af[1][3], bB + 2);
        mma16816(Bt0A, af[0][4], bC);      mma16816(Bt1A, af[1][4], bC);
    }
    // CRITICAL: all warps must finish reading HsB (prologue) before iteration 0's
    // S1 overwrites HsB (epilogue-B h rows + feeder x rows). Without this barrier
    // the backward scan's step-0 corruption lands in out_b[T-1], which l2 consumes
    // at its FINAL step (no decay) -> logits error.
    __syncthreads();

    for (int t = 0; t < TT; t++) {
        // ================= S1: ldsm+mma A ; epilogue B =================
        uint32_t aA[4], aB[4], aC[2];
        ldsm4t(aA, adrA1); ldsm4t(aB, adrA2); ldsm2t(aC, adrA3);

        // epilogue B (acc from previous phase — latency already covered)
        {
            float iv = sig_h (Bt0A[0] + Bt0B[0] + bi);
            float fv = sig_h (Bt0A[2] + Bt0B[2] + bfv);
            float gv = tanh_f(Bt1A[0] + Bt1B[0] + bg);
            float ov = sig_h (Bt1A[2] + Bt1B[2] + bo);
            cB = fmaf(fv, cB, iv * gv);
            float h = ov * tanh_f(cB);
            __half hh = hi_h(h);
            *(__half2*)&HsB[j * 8 + 2 * sl] = __halves2half2(hh, hh);
            *outB = hh; outB += step * 128;
        }
        if (xfd && xg) {
            __half hn = hi_h(vn), ln = lo_h(vn);
            *(__half2*)&HsB[(64 + comp) * 8 + 2 * fs] = __halves2half2(hn, hn);
            *(__half2*)&HsB[(68 + comp) * 8 + 2 * fs] = __halves2half2(ln, ln);
            vn = vi;
            vi = (t + 3 < TT) ? __ldg(xp + (size_t)(t + 3) * step * 4) : 0.f;
        }

        float At0A[4], At0B[4], At1A[4], At1B[4];
#pragma unroll
        for (int q = 0; q < 4; q++) { At0A[q] = 0.f; At0B[q] = 0.f; At1A[q] = 0.f; At1B[q] = 0.f; }
        mma16816(At0A, af[0][0], aA);      mma16816(At1A, af[1][0], aA);
        mma16816(At0A, af[0][1], aA + 2);  mma16816(At1A, af[1][1], aA + 2);
        mma16816(At0B, af[0][2], aB);      mma16816(At1B, af[1][2], aB);
        mma16816(At0B, af[0][3], aB + 2);  mma16816(At1B, af[1][3], aB + 2);
        mma16816(At0A, af[0][4], aC);      mma16816(At1A, af[1][4], aC);

        __syncthreads();

        // ================= S2: ldsm+mma B ; epilogue A =================
        uint32_t bA[4], bB[4], bC[2];
        ldsm4t(bA, adrB1); ldsm4t(bB, adrB2); ldsm2t(bC, adrB3);

        {
            float iv = sig_h (At0A[0] + At0B[0] + bi);
            float fv = sig_h (At0A[2] + At0B[2] + bfv);
            float gv = tanh_f(At1A[0] + At1B[0] + bg);
            float ov = sig_h (At1A[2] + At1B[2] + bo);
            cA = fmaf(fv, cA, iv * gv);
            float h = ov * tanh_f(cA);
            __half hh = hi_h(h);
            *(__half2*)&HsA[j * 8 + 2 * sl] = __halves2half2(hh, hh);
            *outA = hh; outA += step * 128;
        }
        if (xfd && !xg) {
            __half hn = hi_h(vn), ln = lo_h(vn);
            *(__half2*)&HsA[(64 + comp) * 8 + 2 * fs] = __halves2half2(hn, hn);
            *(__half2*)&HsA[(68 + comp) * 8 + 2 * fs] = __halves2half2(ln, ln);
            vn = vi;
            vi = (t + 3 < TT) ? __ldg(xp + (size_t)(t + 3) * step * 4) : 0.f;
        }

#pragma unroll
        for (int q = 0; q < 4; q++) { Bt0A[q] = 0.f; Bt0B[q] = 0.f; Bt1A[q] = 0.f; Bt1B[q] = 0.f; }
        mma16816(Bt0A, af[0][0], bA);      mma16816(Bt1A, af[1][0], bA);
        mma16816(Bt0A, af[0][1], bA + 2);  mma16816(Bt1A, af[1][1], bA + 2);
        mma16816(Bt0B, af[0][2], bB);      mma16816(Bt1B, af[1][2], bB);
        mma16816(Bt0B, af[0][3], bB + 2);  mma16816(Bt1B, af[1][3], bB + 2);
        mma16816(Bt0A, af[0][4], bC);      mma16816(Bt1A, af[1][4], bC);

        __syncthreads();
    }
}

// =====================================================================
// pre2 GEMM (unchanged): g_pre2p[m,n2] = out1h · B2i + bias
// =====================================================================
#define ASG 136
__global__ __launch_bounds__(256, 2)
void pre2_gemm(const float* __restrict__ b2)
{
    const int m0 = blockIdx.x * 128;
    const int tid = threadIdx.x, lane = tid & 31, w = tid >> 5;

    __shared__ __half As[128 * ASG];

    {
        const uint4* src = (const uint4*)(g_out1h + (size_t)m0 * 128);
        for (int i = tid; i < 128 * 16; i += 256) {
            int rr = i >> 4, cc = i & 15;
            *(uint4*)&As[rr * ASG + cc * 8] = __ldg(src + i);
        }
    }
    __syncthreads();

    const uint32_t aaddr = smem_u32(As) + (((w * 16) + (lane & 15)) * ASG + (lane >> 4) * 8) * 2;

    float* outp = g_pre2p + (size_t)(m0 + w * 16) * 256;
    const int row0 = lane >> 2;

#pragma unroll 1
    for (int ng = 0; ng < 8; ng++) {
        uint32_t bfr[4][8][2];
#pragma unroll
        for (int tt = 0; tt < 4; tt++) {
            const int n = ng * 32 + tt * 8 + (lane >> 2);
#pragma unroll
            for (int kt = 0; kt < 8; kt++) {
                const __half* p = g_B2i + (size_t)n * 128 + kt * 16 + 2 * (lane & 3);
                bfr[tt][kt][0] = *(const uint32_t*)p;
                bfr[tt][kt][1] = *(const uint32_t*)(p + 8);
            }
        }

        float acc[4][4];
#pragma unroll
        for (int i = 0; i < 4; i++) { acc[i][0] = 0.f; acc[i][1] = 0.f; acc[i][2] = 0.f; acc[i][3] = 0.f; }
#pragma unroll
        for (int kt = 0; kt < 8; kt++) {
            uint32_t a[4];
            ldsm4(a, aaddr + kt * 32);
            mma16816(acc[0], a, bfr[0][kt]);
            mma16816(acc[1], a, bfr[1][kt]);
            mma16816(acc[2], a, bfr[2][kt]);
            mma16816(acc[3], a, bfr[3][kt]);
        }

#pragma unroll
        for (int tt = 0; tt < 4; tt++) {
            const int col = ng * 32 + tt * 8 + 2 * (lane & 3);
            const int ra = (col & 3) * 64 + (col >> 2);
            const int rb = ((col + 1) & 3) * 64 + ((col + 1) >> 2);
            const float sa = ((col & 3) == 2) ? 1.f : 0.5f;
            const float ba = __ldg(b2 + ra) * sa;
            const float bb = __ldg(b2 + rb) * 0.5f;
            float2 v0 = make_float2(acc[tt][0] + ba, acc[tt][1] + bb);
            float2 v1 = make_float2(acc[tt][2] + ba, acc[tt][3] + bb);
            *(float2*)(outp + (size_t)row0 * 256 + col)       = v0;
            *(float2*)(outp + (size_t)(row0 + 8) * 256 + col) = v1;
        }
    }
}

// =====================================================================
// Layer-2 scan (flipped + pipelined): 8 samples/block (2 groups), 32 blocks.
// =====================================================================
#define HR2 64
__global__ __launch_bounds__(256, 1)
void l2_scan(const float* __restrict__ Whh2,
             const float* __restrict__ Wfc, const float* __restrict__ bfc,
             float* __restrict__ out)
{
    const int s0  = blockIdx.x * 8;
    const int tid = threadIdx.x, lane = tid & 31, w = tid >> 5;

    __shared__ __half HsA[HR2 * 8];
    __shared__ __half HsB[HR2 * 8];
    __shared__ float  sred[8 * 64];

    for (int i = tid; i < HR2 * 8; i += 256) { HsA[i] = __ushort_as_half(0); HsB[i] = __ushort_as_half(0); }

    const int jr = lane >> 2, j = w * 8 + jr, sl = lane & 3;
    const int k0 = 2 * (lane & 3);

    uint32_t af[2][4][4];
#pragma unroll
    for (int tt = 0; tt < 2; tt++) {
        const int rA = (tt == 0 ? 0 : 2) * 64 + j;
        const int rB = (tt == 0 ? 1 : 3) * 64 + j;
        const float sA = (tt == 1) ? 1.f : 0.5f;
        const float sB = 0.5f;
#pragma unroll
        for (int kt = 0; kt < 4; kt++) {
            const float* pA = Whh2 + rA * 64 + kt * 16;
            const float* pB = Whh2 + rB * 64 + kt * 16;
            af[tt][kt][0] = pack2(sA * pA[k0],     sA * pA[k0 + 1]);
            af[tt][kt][1] = pack2(sB * pB[k0],     sB * pB[k0 + 1]);
            af[tt][kt][2] = pack2(sA * pA[k0 + 8], sA * pA[k0 + 9]);
            af[tt][kt][3] = pack2(sB * pB[k0 + 8], sB * pB[k0 + 9]);
        }
    }
    const float wfc_ = __ldg(Wfc + j);

    const uint32_t baseA = smem_u32(HsA), baseB = smem_u32(HsB);
    const uint32_t adrA1 = baseA + lane * 16;
    const uint32_t adrA2 = baseA + (32 + lane) * 16;
    const uint32_t adrB1 = baseB + lane * 16;
    const uint32_t adrB2 = baseB + (32 + lane) * 16;

    // pre2 streams for both groups, depth-3 prefetch each
    const float* ppA = g_pre2p + (size_t)(s0 + sl) * TT * 256 + j * 4;
    const float* ppB = g_pre2p + (size_t)(s0 + 4 + sl) * TT * 256 + j * 4;
    float4 pcA = *(const float4*)ppA, pnA = *(const float4*)(ppA + 256), piA = *(const float4*)(ppA + 512);
    float4 pcB = *(const float4*)ppB, pnB = *(const float4*)(ppB + 256), piB = *(const float4*)(ppB + 512);
    __syncthreads();

    float cA = 0.f, cB = 0.f;
    float hA = 0.f, hB = 0.f;

    // prologue: B's step-0 matvec (h=0 -> zero sums, exact)
    float Bt0A[4], Bt0B[4], Bt1A[4], Bt1B[4];
#pragma unroll
    for (int q = 0; q < 4; q++) { Bt0A[q] = 0.f; Bt0B[q] = 0.f; Bt1A[q] = 0.f; Bt1B[q] = 0.f; }
    {
        uint32_t bA[4], bB[4];
        ldsm4t(bA, adrB1); ldsm4t(bB, adrB2);
        mma16816(Bt0A, af[0][0], bA);      mma16816(Bt1A, af[1][0], bA);
        mma16816(Bt0A, af[0][1], bA + 2);  mma16816(Bt1A, af[1][1], bA + 2);
        mma16816(Bt0B, af[0][2], bB);      mma16816(Bt1B, af[1][2], bB);
        mma16816(Bt0B, af[0][3], bB + 2);  mma16816(Bt1B, af[1][3], bB + 2);
    }
    // CRITICAL: same prologue-vs-S1(t=0) HsB write race as l1 — fence it.
    __syncthreads();

    for (int t = 0; t < TT; t++) {
        // ================= S1 =================
        uint32_t aA[4], aB[4];
        ldsm4t(aA, adrA1); ldsm4t(aB, adrA2);

        {
            float iv = sig_h (Bt0A[0] + Bt0B[0] + pcB.x);
            float fv = sig_h (Bt0A[2] + Bt0B[2] + pcB.y);
            float gv = tanh_f(Bt1A[0] + Bt1B[0] + pcB.z);
            float ov = sig_h (Bt1A[2] + Bt1B[2] + pcB.w);
            cB = fmaf(fv, cB, iv * gv);
            hB = ov * tanh_f(cB);
            __half hh = hi_h(hB);
            *(__half2*)&HsB[j * 8 + 2 * sl] = __halves2half2(hh, hh);
        }
        pcB = pnB; pnB = piB;
        piB = (t + 3 < TT) ? *(const float4*)(ppB + (size_t)(t + 3) * 256)
                           : make_float4(0.f, 0.f, 0.f, 0.f);

        float At0A[4], At0B[4], At1A[4], At1B[4];
#pragma unroll
        for (int q = 0; q < 4; q++) { At0A[q] = 0.f; At0B[q] = 0.f; At1A[q] = 0.f; At1B[q] = 0.f; }
        mma16816(At0A, af[0][0], aA);      mma16816(At1A, af[1][0], aA);
        mma16816(At0A, af[0][1], aA + 2);  mma16816(At1A, af[1][1], aA + 2);
        mma16816(At0B, af[0][2], aB);      mma16816(At1B, af[1][2], aB);
        mma16816(At0B, af[0][3], aB + 2);  mma16816(At1B, af[1][3], aB + 2);

        __syncthreads();

        // ================= S2 =================
        uint32_t bA[4], bB[4];
        ldsm4t(bA, adrB1); ldsm4t(bB, adrB2);

        {
            float iv = sig_h (At0A[0] + At0B[0] + pcA.x);
            float fv = sig_h (At0A[2] + At0B[2] + pcA.y);
            float gv = tanh_f(At1A[0] + At1B[0] + pcA.z);
            float ov = sig_h (At1A[2] + At1B[2] + pcA.w);
            cA = fmaf(fv, cA, iv * gv);
            hA = ov * tanh_f(cA);
            __half hh = hi_h(hA);
            *(__half2*)&HsA[j * 8 + 2 * sl] = __halves2half2(hh, hh);
        }
        pcA = pnA; pnA = piA;
        piA = (t + 3 < TT) ? *(const float4*)(ppA + (size_t)(t + 3) * 256)
                           : make_float4(0.f, 0.f, 0.f, 0.f);

#pragma unroll
        for (int q = 0; q < 4; q++) { Bt0A[q] = 0.f; Bt0B[q] = 0.f; Bt1A[q] = 0.f; Bt1B[q] = 0.f; }
        mma16816(Bt0A, af[0][0], bA);      mma16816(Bt1A, af[1][0], bA);
        mma16816(Bt0A, af[0][1], bA + 2);  mma16816(Bt1A, af[1][1], bA + 2);
        mma16816(Bt0B, af[0][2], bB);      mma16816(Bt1B, af[1][2], bB);
        mma16816(Bt0B, af[0][3], bB + 2);  mma16816(Bt1B, af[1][3], bB + 2);

        __syncthreads();
    }

    // fused FC on final h of both groups
    sred[sl * 64 + j]       = hA * wfc_;
    sred[(4 + sl) * 64 + j] = hB * wfc_;
    __syncthreads();
    if (tid < 8) {
        float acc = __ldg(bfc);
#pragma unroll
        for (int k = 0; k < 64; k++) acc += sred[tid * 64 + k];
        out[s0 + tid] = acc;
    }
}

// =====================================================================
extern "C" void kernel_launch(void* const* d_in, const int* in_sizes, int n_in,
                              void* d_out, int out_size)
{
    const float* x     = (const float*)d_in[0];
    const float* Wih_f = (const float*)d_in[1];
    const float* Whh_f = (const float*)d_in[2];
    const float* b_f   = (const float*)d_in[3];
    const float* Wih_b = (const float*)d_in[4];
    const float* Whh_b = (const float*)d_in[5];
    const float* b_b   = (const float*)d_in[6];
    const float* Wih2  = (const float*)d_in[7];
    const float* Whh2  = (const float*)d_in[8];
    const float* b2    = (const float*)d_in[9];
    const float* Wfc   = (const float*)d_in[10];
    const float* bfc   = (const float*)d_in[11];
    float* out = (float*)d_out;

    build_B2<<<256, 128>>>(Wih2);
    l1_scan<<<64, 256>>>(x, Wih_f, Whh_f, b_f, Wih_b, Whh_b, b_b);
    pre2_gemm<<<(BB * TT) / 128, 256>>>(b2);
    l2_scan<<<32, 256>>>(Whh2, Wfc, bfc, out);
}